// round 2
// baseline (speedup 1.0000x reference)
#include <cuda_runtime.h>

// Shapes: lx_in/ux_in (32768 rows x 1024), lc/uc (32768), x_min/x_max (1024).
// Outputs concatenated in d_out: [lx_out | ux_out | lc_out | uc_out].
//
// One WARP per row: 32 lanes x 8 float4 = 1024 floats. Reduction is a pure
// warp butterfly -> zero __syncthreads, zero smem, fully independent warps.
// Each lane retains its lv[8]/uv[8] in registers across the reduction and
// rescales them for the store (each input byte read exactly once from DRAM).

#define NROWS 32768
#define INNER 1024
#define F4_PER_ROW (INNER / 4)      // 256
#define CHUNKS 8                    // per lane: 8 float4 per array
#define WARPS_PER_BLOCK 8
#define NTHREADS (WARPS_PER_BLOCK * 32)

__global__ __launch_bounds__(NTHREADS)
void crown_relu_warprow(const float* __restrict__ lx_in,
                        const float* __restrict__ ux_in,
                        const float* __restrict__ lc_in,
                        const float* __restrict__ uc_in,
                        const float* __restrict__ x_min,
                        const float* __restrict__ x_max,
                        float* __restrict__ lx_out,
                        float* __restrict__ ux_out,
                        float* __restrict__ lc_out,
                        float* __restrict__ uc_out)
{
    const int wid  = threadIdx.x >> 5;
    const int lane = threadIdx.x & 31;
    const int row  = blockIdx.x * WARPS_PER_BLOCK + wid;

    const long long base4 = (long long)row * F4_PER_ROW;
    const float4* __restrict__ lx4 = reinterpret_cast<const float4*>(lx_in) + base4;
    const float4* __restrict__ ux4 = reinterpret_cast<const float4*>(ux_in) + base4;
    const float4* __restrict__ mn4 = reinterpret_cast<const float4*>(x_min);
    const float4* __restrict__ mx4 = reinterpret_cast<const float4*>(x_max);

    // Front-batched loads: 16 independent LDG.128 per lane (deep MLP).
    float4 lv[CHUNKS], uv[CHUNKS];
    #pragma unroll
    for (int i = 0; i < CHUNKS; i++) {
        const int idx = i * 32 + lane;
        lv[i] = lx4[idx];
        uv[i] = ux4[idx];
    }

    // Reduce: mask_lower*lx == min(lx*mn, lx*mx); mask_upper*ux == max(...).
    float sl = 0.0f, su = 0.0f;
    #pragma unroll
    for (int i = 0; i < CHUNKS; i++) {
        const int idx = i * 32 + lane;
        const float4 mn = mn4[idx];   // L1/L2-resident (8 KB total)
        const float4 mx = mx4[idx];
        sl += fminf(lv[i].x * mn.x, lv[i].x * mx.x)
            + fminf(lv[i].y * mn.y, lv[i].y * mx.y)
            + fminf(lv[i].z * mn.z, lv[i].z * mx.z)
            + fminf(lv[i].w * mn.w, lv[i].w * mx.w);
        su += fmaxf(uv[i].x * mn.x, uv[i].x * mx.x)
            + fmaxf(uv[i].y * mn.y, uv[i].y * mx.y)
            + fmaxf(uv[i].z * mn.z, uv[i].z * mx.z)
            + fmaxf(uv[i].w * mn.w, uv[i].w * mx.w);
    }

    // Butterfly reduction: every lane ends with the full sums.
    #pragma unroll
    for (int off = 16; off > 0; off >>= 1) {
        sl += __shfl_xor_sync(0xffffffffu, sl, off);
        su += __shfl_xor_sync(0xffffffffu, su, off);
    }

    const float lc = lc_in[row];   // uniform per warp -> broadcast load
    const float uc = uc_in[row];
    const float l = sl + lc;
    const float u = su + uc;

    const bool  alive = (l >= 0.0f);
    const bool  cross = (l < 0.0f) && (u > 0.0f);
    const float slope = cross ? fminf(fmaxf(u / (u - l), 0.0f), 1.0f) : 1.0f;

    const float fl = alive ? 1.0f : 0.0f;
    const float fu = alive ? 1.0f : (cross ? slope : 0.0f);

    if (lane == 0) {
        lc_out[row] = fl * lc;
        uc_out[row] = alive ? uc : (cross ? (slope * uc - slope * l) : 0.0f);
    }

    // Rescale register-resident values and stream out.
    float4* __restrict__ lo4 = reinterpret_cast<float4*>(lx_out) + base4;
    float4* __restrict__ uo4 = reinterpret_cast<float4*>(ux_out) + base4;
    #pragma unroll
    for (int i = 0; i < CHUNKS; i++) {
        const int idx = i * 32 + lane;
        float4 lo, uo;
        lo.x = fl * lv[i].x; lo.y = fl * lv[i].y;
        lo.z = fl * lv[i].z; lo.w = fl * lv[i].w;
        uo.x = fu * uv[i].x; uo.y = fu * uv[i].y;
        uo.z = fu * uv[i].z; uo.w = fu * uv[i].w;
        lo4[idx] = lo;
        uo4[idx] = uo;
    }
}

extern "C" void kernel_launch(void* const* d_in, const int* in_sizes, int n_in,
                              void* d_out, int out_size)
{
    const float* lx_in = (const float*)d_in[0];
    const float* ux_in = (const float*)d_in[1];
    const float* lc_in = (const float*)d_in[2];
    const float* uc_in = (const float*)d_in[3];
    const float* x_min = (const float*)d_in[4];
    const float* x_max = (const float*)d_in[5];

    float* out = (float*)d_out;
    const long long big = (long long)NROWS * INNER;   // 33,554,432
    float* lx_out = out;
    float* ux_out = out + big;
    float* lc_out = out + 2 * big;
    float* uc_out = out + 2 * big + NROWS;

    crown_relu_warprow<<<NROWS / WARPS_PER_BLOCK, NTHREADS>>>(
        lx_in, ux_in, lc_in, uc_in, x_min, x_max,
        lx_out, ux_out, lc_out, uc_out);
}

// round 3
// speedup vs baseline: 1.1171x; 1.1171x over previous
#include <cuda_runtime.h>

// Shapes: lx_in/ux_in (32768 rows x 1024), lc/uc (32768), x_min/x_max (1024).
// Outputs concatenated in d_out: [lx_out | ux_out | lc_out | uc_out].
//
// One block (256 threads) per row, one float4 per thread per array.
// Single __syncthreads; every thread redundantly finalizes fl/fu.
// Streaming (.cs) hints on bulk loads/stores to keep L2 clean.

#define NROWS 32768
#define INNER 1024
#define NTHREADS 256
#define NWARPS (NTHREADS / 32)

__device__ __forceinline__ float4 ldcs4(const float4* p) {
    return __ldcs(p);
}
__device__ __forceinline__ void stcs4(float4* p, float4 v) {
    __stcs(p, v);
}

__global__ __launch_bounds__(NTHREADS)
void crown_relu_kernel(const float* __restrict__ lx_in,
                       const float* __restrict__ ux_in,
                       const float* __restrict__ lc_in,
                       const float* __restrict__ uc_in,
                       const float* __restrict__ x_min,
                       const float* __restrict__ x_max,
                       float* __restrict__ lx_out,
                       float* __restrict__ ux_out,
                       float* __restrict__ lc_out,
                       float* __restrict__ uc_out)
{
    const int row = blockIdx.x;
    const int t   = threadIdx.x;
    const long long base4 = (long long)row * (INNER / 4);

    const float4* lx4 = reinterpret_cast<const float4*>(lx_in) + base4;
    const float4* ux4 = reinterpret_cast<const float4*>(ux_in) + base4;
    const float4* mn4 = reinterpret_cast<const float4*>(x_min);
    const float4* mx4 = reinterpret_cast<const float4*>(x_max);

    // Streaming loads for the 1-touch bulk data; normal (caching) loads for
    // the hot 8KB min/max tables.
    float4 lv = ldcs4(lx4 + t);
    float4 uv = ldcs4(ux4 + t);
    float4 mn = __ldg(mn4 + t);
    float4 mx = __ldg(mx4 + t);

    // mask_lower*lx == min(lx*mn, lx*mx); mask_upper*ux == max(...).
    float sl = fminf(lv.x * mn.x, lv.x * mx.x)
             + fminf(lv.y * mn.y, lv.y * mx.y)
             + fminf(lv.z * mn.z, lv.z * mx.z)
             + fminf(lv.w * mn.w, lv.w * mx.w);
    float su = fmaxf(uv.x * mn.x, uv.x * mx.x)
             + fmaxf(uv.y * mn.y, uv.y * mx.y)
             + fmaxf(uv.z * mn.z, uv.z * mx.z)
             + fmaxf(uv.w * mn.w, uv.w * mx.w);

    // Warp butterfly (lane0 has warp sum; butterfly keeps it branch-free).
    #pragma unroll
    for (int off = 16; off > 0; off >>= 1) {
        sl += __shfl_xor_sync(0xffffffffu, sl, off);
        su += __shfl_xor_sync(0xffffffffu, su, off);
    }

    __shared__ float s_l[NWARPS];
    __shared__ float s_u[NWARPS];
    const int lane = t & 31;
    const int wid  = t >> 5;
    if (lane == 0) { s_l[wid] = sl; s_u[wid] = su; }
    __syncthreads();   // the ONLY barrier

    // Every thread redundantly finalizes -> no second barrier, no single-
    // thread serial chain gating the stores.
    const float lc = lc_in[row];
    const float uc = uc_in[row];
    float l = lc, u = uc;
    #pragma unroll
    for (int w = 0; w < NWARPS; w++) { l += s_l[w]; u += s_u[w]; }

    const bool  alive = (l >= 0.0f);
    const bool  cross = (l < 0.0f) && (u > 0.0f);
    const float slope = cross ? fminf(fmaxf(u / (u - l), 0.0f), 1.0f) : 1.0f;

    const float fl = alive ? 1.0f : 0.0f;
    const float fu = alive ? 1.0f : (cross ? slope : 0.0f);

    if (t == 0) {
        lc_out[row] = fl * lc;
        uc_out[row] = alive ? uc : (cross ? (slope * uc - slope * l) : 0.0f);
    }

    float4 lo, uo;
    lo.x = fl * lv.x; lo.y = fl * lv.y; lo.z = fl * lv.z; lo.w = fl * lv.w;
    uo.x = fu * uv.x; uo.y = fu * uv.y; uo.z = fu * uv.z; uo.w = fu * uv.w;

    stcs4(reinterpret_cast<float4*>(lx_out) + base4 + t, lo);
    stcs4(reinterpret_cast<float4*>(ux_out) + base4 + t, uo);
}

extern "C" void kernel_launch(void* const* d_in, const int* in_sizes, int n_in,
                              void* d_out, int out_size)
{
    const float* lx_in = (const float*)d_in[0];
    const float* ux_in = (const float*)d_in[1];
    const float* lc_in = (const float*)d_in[2];
    const float* uc_in = (const float*)d_in[3];
    const float* x_min = (const float*)d_in[4];
    const float* x_max = (const float*)d_in[5];

    float* out = (float*)d_out;
    const long long big = (long long)NROWS * INNER;   // 33,554,432
    float* lx_out = out;
    float* ux_out = out + big;
    float* lc_out = out + 2 * big;
    float* uc_out = out + 2 * big + NROWS;

    crown_relu_kernel<<<NROWS, NTHREADS>>>(lx_in, ux_in, lc_in, uc_in,
                                           x_min, x_max,
                                           lx_out, ux_out, lc_out, uc_out);
}